// round 15
// baseline (speedup 1.0000x reference)
#include <cuda_runtime.h>
#include <cuda_bf16.h>
#include <cstdint>

// ---------------- problem constants ----------------
#define NPRED 1200
#define NTGT  256
#define NCLS  80
#define HW    128
#define SRC   256
#define PIX   16384
#define KTOT  16384
#define MROWS 2400      // rows 0..1199: X (logits), 1200..2399: sigmoid(X)

// ---------------- GEMM config (legacy mma.sync bf16, sm_100-safe) ----------------
#define BM     128
#define BN     256
#define BK     64                 // 128B rows in smem
#define SPLITK 7
#define KS     2368               // ceil(16384/7/64)*64 ; last split gets 2176
#define MT     19                 // ceil(2400/128)
#define STAGES 4
#define ABYTES (BM * 128)         // 16 KB
#define BBYTES (BN * 128)         // 32 KB
#define STGB   (ABYTES + BBYTES)  // 48 KB
#define SMEMSZ (1024 + STAGES * STGB)   // ~193 KB

// resize/convert fused-prep chunking (convert blocks FIRST: heavier -> LPT)
#define RCH    8                  // output rows per resize block
#define NCHUNK (HW / RCH)         // 16
#define RZBLKS (NTGT * NCHUNK)    // 4096 resize blocks
#define PREPBLKS (RZBLKS + NPRED) // 1200 convert + 4096 resize

// ---------------- scratch (device globals; no allocs) ----------------
__device__ __align__(16) __nv_bfloat16 g_Ab[(size_t)MROWS * KTOT];   // 78.6 MB
__device__ __align__(16) __nv_bfloat16 g_Tb[(size_t)NTGT * KTOT];    //  8.4 MB
__device__ __align__(16) float g_D[SPLITK][(size_t)MROWS * NTGT];    // 17.2 MB
__device__ float g_tsum16[NCHUNK * NTGT];   // chunk-major: [c][m] for coalesced assemble reads
__device__ float g_ssum[NPRED];
__device__ float g_sigsum[NPRED];

// ---------------- PTX helpers ----------------
__device__ __forceinline__ uint32_t smem_u32(const void* p) {
    uint32_t a;
    asm("{ .reg .u64 t; cvta.to.shared.u64 t, %1; cvt.u32.u64 %0, t; }" : "=r"(a) : "l"(p));
    return a;
}
__device__ __forceinline__ void cp16(uint32_t sdst, const void* src, int nbytes) {
    asm volatile("cp.async.cg.shared.global [%0], [%1], 16, %2;\n"
                 ::"r"(sdst), "l"(src), "r"(nbytes));
}
__device__ __forceinline__ void ldsm4(uint32_t* r, uint32_t addr) {
    asm volatile("ldmatrix.sync.aligned.m8n8.x4.shared.b16 {%0,%1,%2,%3}, [%4];"
                 : "=r"(r[0]), "=r"(r[1]), "=r"(r[2]), "=r"(r[3]) : "r"(addr));
}
__device__ __forceinline__ void mma16816(float* d, const uint32_t* a, const uint32_t* b) {
    asm volatile(
        "mma.sync.aligned.m16n8k16.row.col.f32.bf16.bf16.f32 "
        "{%0,%1,%2,%3}, {%4,%5,%6,%7}, {%8,%9}, {%0,%1,%2,%3};\n"
        : "+f"(d[0]), "+f"(d[1]), "+f"(d[2]), "+f"(d[3])
        : "r"(a[0]), "r"(a[1]), "r"(a[2]), "r"(a[3]), "r"(b[0]), "r"(b[1]));
}

template <int NW>
__device__ __forceinline__ float block_sum(float v) {
    __shared__ float red[NW];
    int lane = threadIdx.x & 31, w = threadIdx.x >> 5;
#pragma unroll
    for (int o = 16; o > 0; o >>= 1) v += __shfl_down_sync(0xffffffffu, v, o);
    if (lane == 0) red[w] = v;
    __syncthreads();
    if (w == 0) {
        v = (lane < NW) ? red[lane] : 0.f;
#pragma unroll
        for (int o = NW / 2; o > 0; o >>= 1) v += __shfl_down_sync(0xffffffffu, v, o);
    }
    return v;  // valid on thread 0
}

// jax.image.resize(antialias=True) 2x-down triangle taps, edge-renormalized.
// Edge renorm is exactly 8/7 (only index 0 and 127 lose one 1/8 tap) -> select, no div.
__device__ __forceinline__ void make_taps(int i, int* j, float* w) {
    const float bw[4] = {0.125f, 0.375f, 0.375f, 0.125f};
    const float inv = (i == 0 || i == HW - 1) ? (8.f / 7.f) : 1.f;
#pragma unroll
    for (int d = 0; d < 4; ++d) {
        int jj = 2 * i - 1 + d;
        bool ok = (jj >= 0) && (jj < SRC);
        j[d] = ok ? jj : 0;
        w[d] = (ok ? bw[d] : 0.f) * inv;
    }
}

// ---------------- kernel 1: fused prep (convert blocks first, then resize) ----------------
// blocks [0, 1200): convert pred row n=b -> bf16 X & sigmoid(X) + rowsums.
// blocks [1200, 5296): separable two-pass resize of target m, row-chunk.
__global__ __launch_bounds__(256) void k_prep(const float* __restrict__ tgt,
                                              const float* __restrict__ pm) {
    __shared__ float raw[2 * RCH + 2][SRC];   // 18 KB (resize path only)
    __shared__ float hbuf[2 * RCH + 2][HW];   //  9 KB

    const int b = blockIdx.x;
    const int tid = threadIdx.x;

    if (b < NPRED) {
        // ---------- convert: 16 elems/thread/iter, 4 front-batched LDG.128 ----------
        const int n = b;
        const float4* src = (const float4*)(pm + (size_t)n * PIX);
        uint4* dx = (uint4*)(g_Ab + (size_t)n * KTOT);
        uint4* ds = (uint4*)(g_Ab + (size_t)(NPRED + n) * KTOT);

        float ssum0 = 0.f, ssum1 = 0.f, gsum0 = 0.f, gsum1 = 0.f;
        // PIX/16 = 1024 16-elem groups; 256 threads -> 4 iters; thread t owns group t + k*256.
#pragma unroll
        for (int it = 0; it < 4; ++it) {
            int g = tid + it * 256;
            // batched loads: 4 consecutive float4 per thread (64B contiguous segment)
            float4 v[4];
#pragma unroll
            for (int q = 0; q < 4; ++q) v[q] = src[g * 4 + q];
            float xs[16] = {v[0].x, v[0].y, v[0].z, v[0].w, v[1].x, v[1].y, v[1].z, v[1].w,
                            v[2].x, v[2].y, v[2].z, v[2].w, v[3].x, v[3].y, v[3].z, v[3].w};
            float sg[16];
#pragma unroll
            for (int c = 0; c < 16; ++c) {
                float xv = xs[c];
                float t = __expf(-fabsf(xv));
                float u = __fdividef(1.f, 1.f + t);   // sigmoid(|x|)
                float lg = __logf(u);                 // = -log(1+t)
                sg[c] = (xv >= 0.f) ? u : 1.f - u;    // sigmoid(x)
                if (c & 1) { gsum1 += sg[c]; ssum1 += fmaxf(xv, 0.f) - lg; }
                else       { gsum0 += sg[c]; ssum0 += fmaxf(xv, 0.f) - lg; }
            }
            uint32_t px[8], ps[8];
#pragma unroll
            for (int q = 0; q < 8; ++q) {
                __nv_bfloat162 bx = __floats2bfloat162_rn(xs[2 * q], xs[2 * q + 1]);
                __nv_bfloat162 bs = __floats2bfloat162_rn(sg[2 * q], sg[2 * q + 1]);
                px[q] = *(uint32_t*)&bx;
                ps[q] = *(uint32_t*)&bs;
            }
            dx[g * 2]     = make_uint4(px[0], px[1], px[2], px[3]);
            dx[g * 2 + 1] = make_uint4(px[4], px[5], px[6], px[7]);
            ds[g * 2]     = make_uint4(ps[0], ps[1], ps[2], ps[3]);
            ds[g * 2 + 1] = make_uint4(ps[4], ps[5], ps[6], ps[7]);
        }
        float s_tot = block_sum<8>(ssum0 + ssum1);
        __syncthreads();
        float g_tot = block_sum<8>(gsum0 + gsum1);
        if (tid == 0) {
            g_ssum[n] = s_tot;
            g_sigsum[n] = g_tot;
        }
    } else {
        // ---------- resize ----------
        const int rb = b - NPRED;
        const int m = rb / NCHUNK;
        const int chunk = rb % NCHUNK;
        const int y0 = chunk * RCH;
        const int rbase = 2 * y0 - 1;
        const float* src = tgt + (size_t)m * (SRC * SRC);
        __nv_bfloat16* dst = g_Tb + (size_t)m * PIX;

        {
            const int NC4 = (2 * RCH + 2) * (SRC / 4);   // 1152
            for (int idx = tid; idx < NC4; idx += 256) {
                int r = idx >> 6, c4 = idx & 63;
                int grow = min(max(rbase + r, 0), SRC - 1);
                float4 v = *(const float4*)(src + (size_t)grow * SRC + c4 * 4);
                *(float4*)&raw[r][c4 * 4] = v;
            }
        }
        __syncthreads();

        {
            const int x = tid & (HW - 1);
            int jx[4]; float wx[4];
            make_taps(x, jx, wx);
            for (int r = tid >> 7; r < 2 * RCH + 2; r += 2) {
                hbuf[r][x] = wx[0] * raw[r][jx[0]] + wx[1] * raw[r][jx[1]] +
                             wx[2] * raw[r][jx[2]] + wx[3] * raw[r][jx[3]];
            }
        }
        __syncthreads();

        float sum = 0.f;
        {
            const int x = tid & (HW - 1);
            const float bw[4] = {0.125f, 0.375f, 0.375f, 0.125f};
            for (int yy = tid >> 7; yy < RCH; yy += 2) {
                int y = y0 + yy;
                float v = 0.f;
#pragma unroll
                for (int d = 0; d < 4; ++d) {
                    int jj = 2 * y - 1 + d;
                    bool ok = (jj >= 0) && (jj < SRC);
                    float w = ok ? bw[d] : 0.f;
                    int sidx = min(max(jj - rbase, 0), 2 * RCH + 1);
                    v += w * hbuf[sidx][x];
                }
                v *= (y == 0 || y == HW - 1) ? (8.f / 7.f) : 1.f;   // exact edge renorm
                dst[y * HW + x] = __float2bfloat16_rn(v);
                sum += v;
            }
        }
        float tot = block_sum<8>(sum);
        if (tid == 0) g_tsum16[chunk * NTGT + m] = tot;   // chunk-major
    }
}

// ---------------- kernel 2: GEMM D[kz] = A(128 x K) @ T^T(256 x K), ldmatrix+mma ----------------
// 4-stage cp.async pipeline, load distance 2, ONE barrier per k-tile
// (S=4, d=2: stage collision needs S|d or S|d+1 — neither holds).
__global__ __launch_bounds__(256, 1) void k_gemm() {
    extern __shared__ char smem[];
    const uint32_t tiles = (smem_u32(smem) + 1023u) & ~1023u;

    const int tid = threadIdx.x;
    const int lane = tid & 31;
    const int wid = tid >> 5;
    const int wm = wid & 1;    // 2 warp-rows of 64
    const int wn = wid >> 1;   // 4 warp-cols of 64
    const int m0 = blockIdx.x * BM;
    const int kz = blockIdx.y;
    const int kbase = kz * KS;
    const int kend = min(kbase + KS, KTOT);
    const int NT = (kend - kbase) / BK;   // 37 or 34

    auto load_tile = [&](int j) {
        int stage = j & (STAGES - 1);
        uint32_t ab = tiles + stage * STGB;
        uint32_t bb = ab + ABYTES;
        int k0 = kbase + j * BK;
#pragma unroll
        for (int i = 0; i < 4; ++i) {
            int idx = tid + (i << 8);
            int row = idx >> 3, c16 = idx & 7;
            int grow = m0 + row;
            const void* src = g_Ab + (size_t)(grow < MROWS ? grow : 0) * KTOT + k0 + c16 * 8;
            uint32_t off = (uint32_t)(row * 128 + ((c16 * 16) ^ ((row & 7) << 4)));
            cp16(ab + off, src, grow < MROWS ? 16 : 0);
        }
#pragma unroll
        for (int i = 0; i < 8; ++i) {
            int idx = tid + (i << 8);
            int row = idx >> 3, c16 = idx & 7;
            const void* src = g_Tb + (size_t)row * KTOT + k0 + c16 * 8;
            uint32_t off = (uint32_t)(row * 128 + ((c16 * 16) ^ ((row & 7) << 4)));
            cp16(bb + off, src, 16);
        }
        asm volatile("cp.async.commit_group;\n" ::: "memory");
    };

    const int arow = wm * 64 + (lane & 7) + (lane & 8);
    const uint32_t acol0 = (uint32_t)(((lane >> 4) & 1) * 16);
    const int brow0 = wn * 64 + (lane & 7) + ((lane >> 1) & 8);
    const uint32_t bcol0 = (uint32_t)((lane & 8) * 2);

    float acc[4][8][4];
#pragma unroll
    for (int a = 0; a < 4; ++a)
#pragma unroll
        for (int b = 0; b < 8; ++b)
#pragma unroll
            for (int c = 0; c < 4; ++c) acc[a][b][c] = 0.f;

    load_tile(0);
    load_tile(1);

#pragma unroll 1
    for (int kt = 0; kt < NT; ++kt) {
        if (kt + 1 < NT) {
            asm volatile("cp.async.wait_group 1;\n" ::: "memory");
        } else {
            asm volatile("cp.async.wait_group 0;\n" ::: "memory");
        }
        __syncthreads();
        if (kt + 2 < NT) load_tile(kt + 2);

        int stage = kt & (STAGES - 1);
        uint32_t ab = tiles + stage * STGB;
        uint32_t bb = ab + ABYTES;

#pragma unroll
        for (int kb = 0; kb < 4; ++kb) {
            uint32_t af[4][4], bf[8][2];
            uint32_t acolb = (uint32_t)(kb * 32) + acol0;
            uint32_t bcolb = (uint32_t)(kb * 32) + bcol0;
#pragma unroll
            for (int mb = 0; mb < 4; ++mb) {
                int r = arow + mb * 16;
                ldsm4(af[mb], ab + (uint32_t)(r * 128) + (acolb ^ ((uint32_t)(r & 7) << 4)));
            }
#pragma unroll
            for (int p = 0; p < 4; ++p) {
                int r = brow0 + p * 16;
                uint32_t tmp[4];
                ldsm4(tmp, bb + (uint32_t)(r * 128) + (bcolb ^ ((uint32_t)(r & 7) << 4)));
                bf[2 * p][0] = tmp[0]; bf[2 * p][1] = tmp[1];
                bf[2 * p + 1][0] = tmp[2]; bf[2 * p + 1][1] = tmp[3];
            }
#pragma unroll
            for (int mb = 0; mb < 4; ++mb)
#pragma unroll
                for (int nb = 0; nb < 8; ++nb) mma16816(acc[mb][nb], af[mb], bf[nb]);
        }
    }

    float* Dp = g_D[kz];
    const int trow = lane >> 2;
    const int tcol = (lane & 3) * 2;
#pragma unroll
    for (int mb = 0; mb < 4; ++mb) {
        int r0 = m0 + wm * 64 + mb * 16 + trow;
        int r1 = r0 + 8;
#pragma unroll
        for (int nb = 0; nb < 8; ++nb) {
            int col = wn * 64 + nb * 8 + tcol;
            if (r0 < MROWS)
                *(float2*)&Dp[(size_t)r0 * NTGT + col] = make_float2(acc[mb][nb][0], acc[mb][nb][1]);
            if (r1 < MROWS)
                *(float2*)&Dp[(size_t)r1 * NTGT + col] = make_float2(acc[mb][nb][2], acc[mb][nb][3]);
        }
    }
}

// ---------------- kernel 3: assemble final cost matrix ----------------
__global__ __launch_bounds__(256) void k_assemble(const float* __restrict__ logits,
                                                  const float* __restrict__ pboxes,
                                                  const int* __restrict__ ids,
                                                  const float* __restrict__ tboxes,
                                                  float* __restrict__ out) {
    int n = blockIdx.x;
    int m = threadIdx.x;

    float4 pb = ((const float4*)pboxes)[n];
    float4 tb = ((const float4*)tboxes)[m];

    float cbbox = fabsf(pb.x - tb.x) + fabsf(pb.y - tb.y) +
                  fabsf(pb.z - tb.z) + fabsf(pb.w - tb.w);

    float p1x = pb.x - 0.5f * pb.z, p1y = pb.y - 0.5f * pb.w;
    float p2x = pb.x + 0.5f * pb.z, p2y = pb.y + 0.5f * pb.w;
    float t1x = tb.x - 0.5f * tb.z, t1y = tb.y - 0.5f * tb.w;
    float t2x = tb.x + 0.5f * tb.z, t2y = tb.y + 0.5f * tb.w;
    float area1 = (p2x - p1x) * (p2y - p1y);
    float area2 = (t2x - t1x) * (t2y - t1y);
    float iw = fmaxf(fminf(p2x, t2x) - fmaxf(p1x, t1x), 0.f);
    float ih = fmaxf(fminf(p2y, t2y) - fmaxf(p1y, t1y), 0.f);
    float inter = iw * ih;
    float uni = area1 + area2 - inter;
    float iou = inter / uni;
    float ew = fmaxf(fmaxf(p2x, t2x) - fminf(p1x, t1x), 0.f);
    float eh = fmaxf(fmaxf(p2y, t2y) - fminf(p1y, t1y), 0.f);
    float ae = ew * eh;
    float cgiou = -(iou - (ae - uni) / ae);

    int id = ids[m];
    float lg = logits[(size_t)n * NCLS + id];
    float cclass = -1.f / (1.f + expf(-lg));

    size_t ix = (size_t)n * NTGT + m;
    size_t is = (size_t)(NPRED + n) * NTGT + m;
    float dX = 0.f, dS = 0.f;
#pragma unroll
    for (int s = 0; s < SPLITK; ++s) {
        dX += g_D[s][ix];
        dS += g_D[s][is];
    }

    float tsum = 0.f;
#pragma unroll
    for (int c = 0; c < NCHUNK; ++c) tsum += g_tsum16[c * NTGT + m];   // coalesced
    float cmask = (g_ssum[n] - dX) * (1.f / (float)PIX);
    float denom = fmaxf(g_sigsum[n] + tsum, 1e-6f) + 1.f;
    float cdice = -(2.f * dS + 1.f) / denom;

    out[ix] = 5.f * cbbox + 2.f * cgiou + 2.f * cclass + 2.f * cmask + 2.f * cdice;
}

// ---------------- launch ----------------
extern "C" void kernel_launch(void* const* d_in, const int* in_sizes, int n_in,
                              void* d_out, int out_size) {
    const float* logits = (const float*)d_in[0];
    const float* pboxes = (const float*)d_in[1];
    const float* pmasks = (const float*)d_in[2];
    const int*   ids    = (const int*)d_in[3];
    const float* tboxes = (const float*)d_in[4];
    const float* tmasks = (const float*)d_in[5];
    float* out = (float*)d_out;

    cudaFuncSetAttribute(k_gemm, cudaFuncAttributeMaxDynamicSharedMemorySize, SMEMSZ);

    k_prep<<<PREPBLKS, 256>>>(tmasks, pmasks);
    k_gemm<<<dim3(MT, SPLITK), 256, SMEMSZ>>>();
    k_assemble<<<NPRED, NTGT>>>(logits, pboxes, ids, tboxes, out);
}